// round 6
// baseline (speedup 1.0000x reference)
#include <cuda_runtime.h>
#include <cstdint>
#include <cstddef>

// Xonv2D: out[b,o,h,w] = sum_{c,kh,kw} x[b,c,h+kh-1,w+kw-1] * W[h,w,o,c,kh,kw] + bias[h,w,o]
// B=4, CIN=COUT=16, K=3, H=W=128. Weights = 151MB streamed once -> HBM-bound.
// Persistent CTAs (304, 2/SM), 256 threads, 3-deep TMA weight ring.
// Round 6: 2 barriers/iter (separate sout), bias prefetch 1 chunk ahead,
// precomputed fill addresses, dynamic ticketed work distribution.

static constexpr int Hc = 128, Wc = 128;
static constexpr int GROUPS = 4096;                      // 4-pixel groups
static constexpr int RING = 3;
static constexpr int FLOATS_PER_PX = 16 * 16 * 9;        // 2304
static constexpr int CHUNK_FLOATS  = 4 * FLOATS_PER_PX;  // 9216
static constexpr int CHUNK_BYTES   = CHUNK_FLOATS * 4;   // 36864
static constexpr int XTILE_FLOATS  = 16 * 3 * 6 * 4;     // 1152
static constexpr int SMEM_X_OFF    = RING * CHUNK_BYTES;            // 110592
static constexpr int SMEM_OUT_OFF  = SMEM_X_OFF + XTILE_FLOATS * 4; // 115200
static constexpr int SMEM_MBAR_OFF = SMEM_OUT_OFF + 256 * 4;        // 116224
static constexpr int SMEM_TKT_OFF  = SMEM_MBAR_OFF + RING * 8;      // 116248
static constexpr int SMEM_TOTAL    = SMEM_TKT_OFF + 8;              // 116256
static constexpr int GRID          = 304;
static constexpr int NT            = 256;

__device__ unsigned g_ticket;

__global__ void reset_kernel() { g_ticket = 2u * GRID; }

__device__ __forceinline__ uint32_t smem_u32(const void* p) {
    return (uint32_t)__cvta_generic_to_shared(p);
}
__device__ __forceinline__ void mbar_init(uint32_t a, uint32_t count) {
    asm volatile("mbarrier.init.shared.b64 [%0], %1;" :: "r"(a), "r"(count) : "memory");
}
__device__ __forceinline__ void mbar_expect_tx(uint32_t a, uint32_t bytes) {
    asm volatile("mbarrier.arrive.expect_tx.shared.b64 _, [%0], %1;" :: "r"(a), "r"(bytes) : "memory");
}
__device__ __forceinline__ void tma_bulk_g2s(uint32_t dst, const void* src, uint32_t bytes, uint32_t mbar) {
    asm volatile("cp.async.bulk.shared::cta.global.mbarrier::complete_tx::bytes [%0], [%1], %2, [%3];"
                 :: "r"(dst), "l"(src), "r"(bytes), "r"(mbar) : "memory");
}
__device__ __forceinline__ void mbar_wait(uint32_t a, uint32_t parity) {
    uint32_t done;
    asm volatile(
        "{\n\t.reg .pred p;\n\t"
        "mbarrier.try_wait.parity.acquire.cta.shared::cta.b64 p, [%1], %2;\n\t"
        "selp.b32 %0, 1, 0, p;\n\t}"
        : "=r"(done) : "r"(a), "r"(parity) : "memory");
    while (!done) {
        asm volatile(
            "{\n\t.reg .pred p;\n\t"
            "mbarrier.try_wait.parity.acquire.cta.shared::cta.b64 p, [%1], %2, 0x989680;\n\t"
            "selp.b32 %0, 1, 0, p;\n\t}"
            : "=r"(done) : "r"(a), "r"(parity) : "memory");
    }
}

__global__ void __launch_bounds__(NT, 2)
xonv2d_kernel(const float* __restrict__ x,
              const float* __restrict__ wts,
              const float* __restrict__ bias,
              float* __restrict__ out)
{
    extern __shared__ char smem[];
    float*  swt   = reinterpret_cast<float*>(smem);
    float*  sx    = reinterpret_cast<float*>(smem + SMEM_X_OFF);
    float4* sx4   = reinterpret_cast<float4*>(smem + SMEM_X_OFF);
    float*  sout  = reinterpret_cast<float*>(smem + SMEM_OUT_OFF);
    float4* sout4 = reinterpret_cast<float4*>(smem + SMEM_OUT_OFF);
    int*    stkt  = reinterpret_cast<int*>(smem + SMEM_TKT_OFF);
    const uint32_t mb = smem_u32(smem + SMEM_MBAR_OFF);

    const int t   = threadIdx.x;
    const int bid = blockIdx.x;

    if (t == 0) {
        #pragma unroll
        for (int s = 0; s < RING; s++) mbar_init(mb + s * 8, 1);
    }
    __syncthreads();

    // Prologue: TMA weight chunks bid (slot0), bid+GRID (slot1). Both < GROUPS.
    if (t == 0) {
        mbar_expect_tx(mb + 0, CHUNK_BYTES);
        tma_bulk_g2s(smem_u32(swt), wts + (size_t)bid * CHUNK_FLOATS, CHUNK_BYTES, mb + 0);
        mbar_expect_tx(mb + 8, CHUNK_BYTES);
        tma_bulk_g2s(smem_u32(swt + CHUNK_FLOATS),
                     wts + (size_t)(bid + GRID) * CHUNK_FLOATS, CHUNK_BYTES, mb + 8);
    }

    // Lane mapping (round-5 verified): o0l=bit0, ch=bits1-3, o0h=bit4; warp: o0m=bit5, px=bits6-7.
    const int o0  = (t & 1) + 2 * ((t >> 4) & 1) + 4 * ((t >> 5) & 1);
    const int ch  = (t >> 1) & 7;
    const int px  = (t >> 6) & 3;
    const int xsw = (ch >> 1) & 3;
    const int wbase_f2 = px * (FLOATS_PER_PX / 2) + o0 * 72 + ch * 9;
    const int xb0 = (2 * ch) * 18 + px;
    const int xb1 = xb0 + 18;

    // Precomputed x-fill constants (loop-invariant across chunks).
    int goff[5], sidx[5], pk[5];
    #pragma unroll
    for (int it = 0; it < 5; it++) {
        const int i = t + it * NT;
        if (i < XTILE_FLOATS) {
            const int wi = i % 6;
            const int r  = (i / 6) % 3;
            const int c  = (i / 18) % 16;
            const int b  = i / 288;
            goff[it] = ((b * 16 + c) * Hc + (r - 1)) * Wc + (wi - 1);
            sidx[it] = ((c * 18 + r * 6 + wi) ^ ((c >> 2) & 3)) * 4 + b;
            pk[it]   = r | (wi << 4);
        }
    }

    int g0 = bid, g1 = bid + GRID;

    // x prefetch for g0.
    float xr[5];
    {
        const int p0 = g0 * 4;
        #pragma unroll
        for (int it = 0; it < 5; it++) {
            const int i = t + it * NT;
            if (i < XTILE_FLOATS) {
                const int hh = (p0 >> 7) + (pk[it] & 15) - 1;
                const int ww = (p0 & 127) + (pk[it] >> 4) - 1;
                xr[it] = ((unsigned)hh < 128u && (unsigned)ww < 128u)
                         ? __ldg(x + goff[it] + p0) : 0.0f;
            }
        }
    }
    // bias prefetch for g0.
    float bs0 = 0.f, bs1 = 0.f, bs2 = 0.f, bs3 = 0.f;
    if (t < 64) {
        const float* bp = bias + (size_t)g0 * 64 + (t & 15);
        bs0 = __ldg(bp); bs1 = __ldg(bp + 16); bs2 = __ldg(bp + 32); bs3 = __ldg(bp + 48);
    }

    for (int j = 0; g0 < GROUPS; j++) {
        const int slot   = j % RING;
        const int parity = (j / RING) & 1;

        // STS x for chunk g0 (prev compute's sx reads finished before last barrier).
        #pragma unroll
        for (int it = 0; it < 5; it++) {
            const int i = t + it * NT;
            if (i < XTILE_FLOATS) sx[sidx[it]] = xr[it];
        }

        // Ticket chunk g2 and TMA it into the slot freed last iteration.
        if (t == 0) {
            const int g2t = (int)atomicAdd(&g_ticket, 1u);
            stkt[0] = g2t;
            if (g2t < GROUPS) {
                const int sn = (j + 2) % RING;
                mbar_expect_tx(mb + sn * 8, CHUNK_BYTES);
                tma_bulk_g2s(smem_u32(swt + sn * CHUNK_FLOATS),
                             wts + (size_t)g2t * CHUNK_FLOATS, CHUNK_BYTES, mb + sn * 8);
            }
        }
        __syncthreads();   // B1: sx ready, ticket visible
        const int g2 = stkt[0];

        // x + bias prefetch for g1 (hidden behind mbar_wait + compute).
        if (g1 < GROUPS) {
            const int p1 = g1 * 4;
            #pragma unroll
            for (int it = 0; it < 5; it++) {
                const int i = t + it * NT;
                if (i < XTILE_FLOATS) {
                    const int hh = (p1 >> 7) + (pk[it] & 15) - 1;
                    const int ww = (p1 & 127) + (pk[it] >> 4) - 1;
                    xr[it] = ((unsigned)hh < 128u && (unsigned)ww < 128u)
                             ? __ldg(x + goff[it] + p1) : 0.0f;
                }
            }
        }
        float bn0 = 0.f, bn1 = 0.f, bn2 = 0.f, bn3 = 0.f;
        if (t < 64 && g1 < GROUPS) {
            const float* bp = bias + (size_t)g1 * 64 + (t & 15);
            bn0 = __ldg(bp); bn1 = __ldg(bp + 16); bn2 = __ldg(bp + 32); bn3 = __ldg(bp + 48);
        }

        mbar_wait(mb + slot * 8, parity);  // weights for g0 ready

        const float2* wp = reinterpret_cast<const float2*>(swt + slot * CHUNK_FLOATS) + wbase_f2;

        float a00 = 0.f, a01 = 0.f, a02 = 0.f, a03 = 0.f;
        float a10 = 0.f, a11 = 0.f, a12 = 0.f, a13 = 0.f;

        #pragma unroll
        for (int k = 0; k < 9; k++) {
            const float2 w0 = wp[k];          // cout o0
            const float2 w1 = wp[k + 576];    // cout o0+8
            #pragma unroll
            for (int e = 0; e < 2; e++) {
                const int f   = 2 * k + e;    // 0..17
                const int cc  = f / 9;
                const int tap = f % 9;
                const int r   = tap / 3;
                const int s   = tap % 3;
                const float4 xv = sx4[((cc ? xb1 : xb0) + r * 6 + s) ^ xsw];
                const float wa = e ? w0.y : w0.x;
                const float wb = e ? w1.y : w1.x;
                a00 += wa * xv.x;  a01 += wa * xv.y;  a02 += wa * xv.z;  a03 += wa * xv.w;
                a10 += wb * xv.x;  a11 += wb * xv.y;  a12 += wb * xv.z;  a13 += wb * xv.w;
            }
        }

        // Reduce over ch (lane bits 1-3).
        #pragma unroll
        for (int m = 2; m <= 8; m <<= 1) {
            a00 += __shfl_xor_sync(0xffffffffu, a00, m);
            a01 += __shfl_xor_sync(0xffffffffu, a01, m);
            a02 += __shfl_xor_sync(0xffffffffu, a02, m);
            a03 += __shfl_xor_sync(0xffffffffu, a03, m);
            a10 += __shfl_xor_sync(0xffffffffu, a10, m);
            a11 += __shfl_xor_sync(0xffffffffu, a11, m);
            a12 += __shfl_xor_sync(0xffffffffu, a12, m);
            a13 += __shfl_xor_sync(0xffffffffu, a13, m);
        }

        if (ch == 0) {
            const int o1 = o0 + 8;
            sout[(0 * 16 + o0) * 4 + px] = a00;
            sout[(1 * 16 + o0) * 4 + px] = a01;
            sout[(2 * 16 + o0) * 4 + px] = a02;
            sout[(3 * 16 + o0) * 4 + px] = a03;
            sout[(0 * 16 + o1) * 4 + px] = a10;
            sout[(1 * 16 + o1) * 4 + px] = a11;
            sout[(2 * 16 + o1) * 4 + px] = a12;
            sout[(3 * 16 + o1) * 4 + px] = a13;
        }
        __syncthreads();   // B2: sout ready (also: all sx/weight reads of chunk g0 done)

        if (t < 64) {
            float4 v = sout4[t];
            v.x += bs0; v.y += bs1; v.z += bs2; v.w += bs3;
            *reinterpret_cast<float4*>(out + (size_t)t * (Hc * Wc) + g0 * 4) = v;
            bs0 = bn0; bs1 = bn1; bs2 = bn2; bs3 = bn3;
        }

        g0 = g1;
        g1 = g2;
    }
}

extern "C" void kernel_launch(void* const* d_in, const int* in_sizes, int n_in,
                              void* d_out, int out_size) {
    const float* x    = (const float*)d_in[0];
    const float* wts  = (const float*)d_in[1];
    const float* bias = (const float*)d_in[2];
    float* out        = (float*)d_out;

    cudaFuncSetAttribute(xonv2d_kernel, cudaFuncAttributeMaxDynamicSharedMemorySize, SMEM_TOTAL);
    reset_kernel<<<1, 1>>>();
    xonv2d_kernel<<<GRID, NT, SMEM_TOTAL>>>(x, wts, bias, out);
}

// round 7
// speedup vs baseline: 1.2211x; 1.2211x over previous
#include <cuda_runtime.h>
#include <cstdint>
#include <cstddef>

// Xonv2D: out[b,o,h,w] = sum_{c,kh,kw} x[b,c,h+kh-1,w+kw-1] * W[h,w,o,c,kh,kw] + bias[h,w,o]
// B=4, CIN=COUT=16, K=3, H=W=128. Weights = 151MB streamed once -> HBM-bound.
// Round 7 = Round 5 (39.7us known-good: 2 CTAs/SM x 256 thr, TMA ring-3,
// conflict-free LDS mappings, sout overlaid on sx, 4 barriers) plus smem-neutral
// wins: bias register prefetch 1 chunk ahead + hoisted x-fill address math.
// smem = 115232 B (2 CTAs/SM boundary is ~116224 -- do not grow).

static constexpr int Hc = 128, Wc = 128;
static constexpr int GROUPS = 4096;                      // 4-pixel groups
static constexpr int RING = 3;
static constexpr int FLOATS_PER_PX = 16 * 16 * 9;        // 2304
static constexpr int CHUNK_FLOATS  = 4 * FLOATS_PER_PX;  // 9216
static constexpr int CHUNK_BYTES   = CHUNK_FLOATS * 4;   // 36864
static constexpr int XTILE_FLOATS  = 16 * 3 * 6 * 4;     // 1152 (sout 256 floats overlaid)
static constexpr int SMEM_X_OFF    = RING * CHUNK_BYTES;            // 110592
static constexpr int SMEM_MBAR_OFF = SMEM_X_OFF + XTILE_FLOATS * 4; // 115200
static constexpr int SMEM_TOTAL    = SMEM_MBAR_OFF + RING * 8 + 8;  // 115232
static constexpr int GRID          = 304;
static constexpr int NT            = 256;

__device__ __forceinline__ uint32_t smem_u32(const void* p) {
    return (uint32_t)__cvta_generic_to_shared(p);
}
__device__ __forceinline__ void mbar_init(uint32_t a, uint32_t count) {
    asm volatile("mbarrier.init.shared.b64 [%0], %1;" :: "r"(a), "r"(count) : "memory");
}
__device__ __forceinline__ void mbar_expect_tx(uint32_t a, uint32_t bytes) {
    asm volatile("mbarrier.arrive.expect_tx.shared.b64 _, [%0], %1;" :: "r"(a), "r"(bytes) : "memory");
}
__device__ __forceinline__ void tma_bulk_g2s(uint32_t dst, const void* src, uint32_t bytes, uint32_t mbar) {
    asm volatile("cp.async.bulk.shared::cta.global.mbarrier::complete_tx::bytes [%0], [%1], %2, [%3];"
                 :: "r"(dst), "l"(src), "r"(bytes), "r"(mbar) : "memory");
}
__device__ __forceinline__ void mbar_wait(uint32_t a, uint32_t parity) {
    uint32_t done;
    asm volatile(
        "{\n\t.reg .pred p;\n\t"
        "mbarrier.try_wait.parity.acquire.cta.shared::cta.b64 p, [%1], %2;\n\t"
        "selp.b32 %0, 1, 0, p;\n\t}"
        : "=r"(done) : "r"(a), "r"(parity) : "memory");
    while (!done) {
        asm volatile(
            "{\n\t.reg .pred p;\n\t"
            "mbarrier.try_wait.parity.acquire.cta.shared::cta.b64 p, [%1], %2, 0x989680;\n\t"
            "selp.b32 %0, 1, 0, p;\n\t}"
            : "=r"(done) : "r"(a), "r"(parity) : "memory");
    }
}

__global__ void __launch_bounds__(NT, 2)
xonv2d_kernel(const float* __restrict__ x,
              const float* __restrict__ wts,
              const float* __restrict__ bias,
              float* __restrict__ out)
{
    extern __shared__ char smem[];
    float*  swt = reinterpret_cast<float*>(smem);
    float*  sx  = reinterpret_cast<float*>(smem + SMEM_X_OFF);
    float4* sx4 = reinterpret_cast<float4*>(smem + SMEM_X_OFF);
    const uint32_t mb = smem_u32(smem + SMEM_MBAR_OFF);

    const int t   = threadIdx.x;
    const int bid = blockIdx.x;

    if (t == 0) {
        #pragma unroll
        for (int s = 0; s < RING; s++) mbar_init(mb + s * 8, 1);
    }
    __syncthreads();

    // Prologue: TMA weight chunks bid (slot0), bid+GRID (slot1).
    if (t == 0) {
        mbar_expect_tx(mb + 0, CHUNK_BYTES);
        tma_bulk_g2s(smem_u32(swt), wts + (size_t)bid * CHUNK_FLOATS, CHUNK_BYTES, mb + 0);
        if (bid + GRID < GROUPS) {
            mbar_expect_tx(mb + 8, CHUNK_BYTES);
            tma_bulk_g2s(smem_u32(swt + CHUNK_FLOATS),
                         wts + (size_t)(bid + GRID) * CHUNK_FLOATS, CHUNK_BYTES, mb + 8);
        }
    }

    // Lane mapping: o0l=bit0, ch=bits1-3 (cin pair), o0h=bit4; warp: o0m=bit5, px=bits6-7.
    const int o0  = (t & 1) + 2 * ((t >> 4) & 1) + 4 * ((t >> 5) & 1);
    const int ch  = (t >> 1) & 7;
    const int px  = (t >> 6) & 3;
    const int xsw = (ch >> 1) & 3;
    const int wbase_f2 = px * (FLOATS_PER_PX / 2) + o0 * 72 + ch * 9;
    const int xb0 = (2 * ch) * 18 + px;
    const int xb1 = xb0 + 18;

    // Precomputed x-fill constants (loop-invariant across chunks).
    int goff[5], sidx[5], rr[5], wwi[5];
    #pragma unroll
    for (int it = 0; it < 5; it++) {
        const int i = t + it * NT;
        if (i < XTILE_FLOATS) {
            const int wi = i % 6;
            const int r  = (i / 6) % 3;
            const int c  = (i / 18) % 16;
            const int b  = i / 288;
            goff[it] = ((b * 16 + c) * Hc + (r - 1)) * Wc + (wi - 1);
            sidx[it] = ((c * 18 + r * 6 + wi) ^ ((c >> 2) & 3)) * 4 + b;
            rr[it]   = r - 1;
            wwi[it]  = wi - 1;
        }
    }

    // ---- x prefetch for first chunk ----
    float xr[5];
    {
        const int p0 = bid * 4;
        const int h0 = p0 >> 7, w0 = p0 & 127;
        #pragma unroll
        for (int it = 0; it < 5; it++) {
            const int i = t + it * NT;
            if (i < XTILE_FLOATS) {
                const int hh = h0 + rr[it];
                const int ww = w0 + wwi[it];
                xr[it] = ((unsigned)hh < 128u && (unsigned)ww < 128u)
                         ? __ldg(x + goff[it] + p0) : 0.0f;
            }
        }
    }
    // ---- bias prefetch for first chunk ----
    float bs0 = 0.f, bs1 = 0.f, bs2 = 0.f, bs3 = 0.f;
    if (t < 64) {
        const float* bp = bias + (size_t)bid * 64 + (t & 15);
        bs0 = __ldg(bp); bs1 = __ldg(bp + 16); bs2 = __ldg(bp + 32); bs3 = __ldg(bp + 48);
    }

    for (int j = 0, gi = bid; gi < GROUPS; j++, gi += GRID) {
        const int slot   = j % RING;
        const int parity = (j / RING) & 1;

        __syncthreads();   // S1: prev sout-read + sx-read done -> sx writable

        // Store prefetched x into sx tile.
        #pragma unroll
        for (int it = 0; it < 5; it++) {
            const int i = t + it * NT;
            if (i < XTILE_FLOATS) sx[sidx[it]] = xr[it];
        }

        // TMA for chunk j+2 into the slot chunk j-1 freed at S1.
        if (t == 0) {
            int gn = gi + (RING - 1) * GRID;
            if (gn < GROUPS) {
                int sn = (j + RING - 1) % RING;
                mbar_expect_tx(mb + sn * 8, CHUNK_BYTES);
                tma_bulk_g2s(smem_u32(swt + sn * CHUNK_FLOATS),
                             wts + (size_t)gn * CHUNK_FLOATS, CHUNK_BYTES, mb + sn * 8);
            }
        }
        __syncthreads();   // S2: sx tile ready

        // Prefetch x + bias for next chunk (hidden behind mbar_wait + compute).
        float bn0 = 0.f, bn1 = 0.f, bn2 = 0.f, bn3 = 0.f;
        {
            const int gn2 = gi + GRID;
            if (gn2 < GROUPS) {
                const int p1 = gn2 * 4;
                const int h0 = p1 >> 7, w0 = p1 & 127;
                #pragma unroll
                for (int it = 0; it < 5; it++) {
                    const int i = t + it * NT;
                    if (i < XTILE_FLOATS) {
                        const int hh = h0 + rr[it];
                        const int ww = w0 + wwi[it];
                        xr[it] = ((unsigned)hh < 128u && (unsigned)ww < 128u)
                                 ? __ldg(x + goff[it] + p1) : 0.0f;
                    }
                }
                if (t < 64) {
                    const float* bp = bias + (size_t)gn2 * 64 + (t & 15);
                    bn0 = __ldg(bp); bn1 = __ldg(bp + 16);
                    bn2 = __ldg(bp + 32); bn3 = __ldg(bp + 48);
                }
            }
        }

        mbar_wait(mb + slot * 8, parity);  // weights for chunk gi ready

        const float2* wp = reinterpret_cast<const float2*>(swt + slot * CHUNK_FLOATS) + wbase_f2;

        float a00 = 0.f, a01 = 0.f, a02 = 0.f, a03 = 0.f;
        float a10 = 0.f, a11 = 0.f, a12 = 0.f, a13 = 0.f;

        #pragma unroll
        for (int k = 0; k < 9; k++) {
            const float2 w0 = wp[k];          // cout o0
            const float2 w1 = wp[k + 576];    // cout o0+8
            #pragma unroll
            for (int e = 0; e < 2; e++) {
                const int f   = 2 * k + e;    // 0..17
                const int cc  = f / 9;
                const int tap = f % 9;
                const int r   = tap / 3;
                const int s   = tap % 3;
                const float4 xv = sx4[((cc ? xb1 : xb0) + r * 6 + s) ^ xsw];
                const float wa = e ? w0.y : w0.x;
                const float wb = e ? w1.y : w1.x;
                a00 += wa * xv.x;  a01 += wa * xv.y;  a02 += wa * xv.z;  a03 += wa * xv.w;
                a10 += wb * xv.x;  a11 += wb * xv.y;  a12 += wb * xv.z;  a13 += wb * xv.w;
            }
        }

        // Reduce over ch (lane bits 1-3): 3 butterflies.
        #pragma unroll
        for (int m = 2; m <= 8; m <<= 1) {
            a00 += __shfl_xor_sync(0xffffffffu, a00, m);
            a01 += __shfl_xor_sync(0xffffffffu, a01, m);
            a02 += __shfl_xor_sync(0xffffffffu, a02, m);
            a03 += __shfl_xor_sync(0xffffffffu, a03, m);
            a10 += __shfl_xor_sync(0xffffffffu, a10, m);
            a11 += __shfl_xor_sync(0xffffffffu, a11, m);
            a12 += __shfl_xor_sync(0xffffffffu, a12, m);
            a13 += __shfl_xor_sync(0xffffffffu, a13, m);
        }

        __syncthreads();   // S3: all sx reads done -> sout (overlaid on sx) writable

        // Stage outputs: sout[(b*16+o)*4 + px], written by ch==0 lanes.
        if (ch == 0) {
            const int o1 = o0 + 8;
            sx[(0 * 16 + o0) * 4 + px] = a00;
            sx[(1 * 16 + o0) * 4 + px] = a01;
            sx[(2 * 16 + o0) * 4 + px] = a02;
            sx[(3 * 16 + o0) * 4 + px] = a03;
            sx[(0 * 16 + o1) * 4 + px] = a10;
            sx[(1 * 16 + o1) * 4 + px] = a11;
            sx[(2 * 16 + o1) * 4 + px] = a12;
            sx[(3 * 16 + o1) * 4 + px] = a13;
        }
        __syncthreads();   // S4: sout ready

        // Coalesced write: thread t<64 -> (b = t>>4, o = t&15), float4 over 4 pixels.
        if (t < 64) {
            float4 v = sx4[t];
            v.x += bs0; v.y += bs1; v.z += bs2; v.w += bs3;
            *reinterpret_cast<float4*>(out + (size_t)t * (Hc * Wc) + gi * 4) = v;
            bs0 = bn0; bs1 = bn1; bs2 = bn2; bs3 = bn3;
        }
    }
}

extern "C" void kernel_launch(void* const* d_in, const int* in_sizes, int n_in,
                              void* d_out, int out_size) {
    const float* x    = (const float*)d_in[0];
    const float* wts  = (const float*)d_in[1];
    const float* bias = (const float*)d_in[2];
    float* out        = (float*)d_out;

    cudaFuncSetAttribute(xonv2d_kernel, cudaFuncAttributeMaxDynamicSharedMemorySize, SMEM_TOTAL);
    xonv2d_kernel<<<GRID, NT, SMEM_TOTAL>>>(x, wts, bias, out);
}